// round 5
// baseline (speedup 1.0000x reference)
#include <cuda_runtime.h>
#include <cuda_bf16.h>

// ContrastivePredictionLoss on GB300.  [design frozen pending first successful bench]
// inputs (metadata order): pred_mean, pred_std, targets — each (64,4,256,256) fp32
// output: scalar fp32 loss.
//
// Stage A: per-batch sums of |pm - tg| and ps. 64 blocks per batch, 256 threads,
//          streaming float4 loads (__ldcs), deterministic block reduction.
// Stage B: one block deterministically folds partials (vectorized float4) and
//          computes the 64x64 pairwise hinge loss.

#define B            64
#define ELEMS_PER_B  262144            // 4*256*256
#define VEC_PER_B    (ELEMS_PER_B / 4) // 65536 float4
#define BLOCKS_PER_B 64
#define VEC_PER_BLK  (VEC_PER_B / BLOCKS_PER_B) // 1024 float4
#define THREADS_A    256
#define VEC_PER_THR  (VEC_PER_BLK / THREADS_A)  // 4 float4 per tensor
#define NWARPS_A     (THREADS_A / 32)           // 8
#define MARGIN       1.0f

__device__ float g_perr[B * BLOCKS_PER_B];
__device__ float g_punc[B * BLOCKS_PER_B];

__global__ __launch_bounds__(THREADS_A)
void cpl_stageA(const float4* __restrict__ pm,
                const float4* __restrict__ ps,
                const float4* __restrict__ tg)
{
    const int batch = blockIdx.y;
    const int blk   = blockIdx.x;
    const int tid   = threadIdx.x;

    const long base = (long)batch * VEC_PER_B + (long)blk * VEC_PER_BLK;

    float se = 0.0f;   // sum |pm - tg|
    float su = 0.0f;   // sum ps

    // Front-batched independent streaming loads -> high MLP; 12 LDG.128/thread.
    float4 m[VEC_PER_THR], t[VEC_PER_THR], s[VEC_PER_THR];
#pragma unroll
    for (int k = 0; k < VEC_PER_THR; k++) {
        long j = base + (long)k * THREADS_A + tid;
        m[k] = __ldcs(&pm[j]);
        t[k] = __ldcs(&tg[j]);
        s[k] = __ldcs(&ps[j]);
    }
#pragma unroll
    for (int k = 0; k < VEC_PER_THR; k++) {
        se += fabsf(m[k].x - t[k].x) + fabsf(m[k].y - t[k].y)
            + fabsf(m[k].z - t[k].z) + fabsf(m[k].w - t[k].w);
        su += s[k].x + s[k].y + s[k].z + s[k].w;
    }

    // Warp reduce
#pragma unroll
    for (int o = 16; o > 0; o >>= 1) {
        se += __shfl_down_sync(0xFFFFFFFFu, se, o);
        su += __shfl_down_sync(0xFFFFFFFFu, su, o);
    }

    __shared__ float serr[NWARPS_A];
    __shared__ float sunc[NWARPS_A];
    const int wid  = tid >> 5;
    const int lane = tid & 31;
    if (lane == 0) { serr[wid] = se; sunc[wid] = su; }
    __syncthreads();

    // Warp 0 folds the 8 per-warp partials via shuffle (parallel, low latency).
    if (wid == 0) {
        float e = (lane < NWARPS_A) ? serr[lane] : 0.0f;
        float u = (lane < NWARPS_A) ? sunc[lane] : 0.0f;
#pragma unroll
        for (int o = 4; o > 0; o >>= 1) {
            e += __shfl_down_sync(0xFFFFFFFFu, e, o);
            u += __shfl_down_sync(0xFFFFFFFFu, u, o);
        }
        if (lane == 0) {
            g_perr[batch * BLOCKS_PER_B + blk] = e;
            g_punc[batch * BLOCKS_PER_B + blk] = u;
        }
    }
}

__global__ __launch_bounds__(256)
void cpl_stageB(float* __restrict__ out)
{
    __shared__ float err[B];
    __shared__ float unc[B];
    __shared__ float red[256];

    const int tid = threadIdx.x;

    // Fold 64 partials per batch with vectorized float4 loads (16 LDG.128,
    // front-batched for MLP), deterministic fixed order.
    if (tid < B) {
        const float4* pe = (const float4*)&g_perr[tid * BLOCKS_PER_B];
        const float4* pu = (const float4*)&g_punc[tid * BLOCKS_PER_B];
        float e = 0.0f, u = 0.0f;
#pragma unroll
        for (int k = 0; k < BLOCKS_PER_B / 4; k++) {
            float4 ev = pe[k];
            float4 uv = pu[k];
            e += (ev.x + ev.y) + (ev.z + ev.w);
            u += (uv.x + uv.y) + (uv.z + uv.w);
        }
        const float inv = 1.0f / (float)ELEMS_PER_B;
        err[tid] = e * inv;
        unc[tid] = u * inv;
    }
    __syncthreads();

    // 64x64 upper-triangular pairwise hinge: 4096 pairs / 256 threads = 16 each.
    float acc = 0.0f;
#pragma unroll
    for (int p = tid; p < B * B; p += 256) {
        int i = p >> 6;       // p / 64
        int j = p & 63;       // p % 64
        if (j > i) {
            float ei = err[i], ej = err[j];
            float ui = unc[i], uj = unc[j];
            float d  = (ei > ej) ? (uj - ui) : (ui - uj);
            acc += fmaxf(d + MARGIN, 0.0f);
        }
    }
    red[tid] = acc;
    __syncthreads();

    // Deterministic tree reduce.
    for (int s = 128; s > 0; s >>= 1) {
        if (tid < s) red[tid] += red[tid + s];
        __syncthreads();
    }

    if (tid == 0) {
        const int num_pairs = B * (B - 1) / 2;   // 2016
        out[0] = red[0] / (float)num_pairs;
    }
}

extern "C" void kernel_launch(void* const* d_in, const int* in_sizes, int n_in,
                              void* d_out, int out_size)
{
    const float4* pm = (const float4*)d_in[0]; // pred_mean
    const float4* ps = (const float4*)d_in[1]; // pred_std
    const float4* tg = (const float4*)d_in[2]; // targets
    float* out = (float*)d_out;

    dim3 grid(BLOCKS_PER_B, B);
    cpl_stageA<<<grid, THREADS_A>>>(pm, ps, tg);
    cpl_stageB<<<1, 256>>>(out);
}